// round 2
// baseline (speedup 1.0000x reference)
#include <cuda_runtime.h>
#include <cstdint>

// Problem constants (local_emb_D: N_NODES=100000, N_HIDDEN=128, N_EDGES=625000)
#define H 128
#define MAX_NODES 100000

// Scratch for normalized embeddings (51.2 MB) — device global, allocation-free.
__device__ float g_e[(size_t)MAX_NODES * H];

// ---------------------------------------------------------------------------
// Pass 1: L2-normalize each row. One warp per row; lane i handles float4 #i.
// ---------------------------------------------------------------------------
__global__ void normalize_rows(const float* __restrict__ emb, int n_nodes) {
    int warp = (blockIdx.x * blockDim.x + threadIdx.x) >> 5;
    int lane = threadIdx.x & 31;
    if (warp >= n_nodes) return;

    const float4* row = reinterpret_cast<const float4*>(emb) + (size_t)warp * (H / 4);
    float4 v = row[lane];

    float s = v.x * v.x + v.y * v.y + v.z * v.z + v.w * v.w;
#pragma unroll
    for (int o = 16; o > 0; o >>= 1) s += __shfl_xor_sync(0xffffffffu, s, o);

    // reference: emb / max(||emb||, 1e-12)
    float inv = 1.0f / fmaxf(sqrtf(s), 1e-12f);

    float4 r = make_float4(v.x * inv, v.y * inv, v.z * inv, v.w * inv);
    reinterpret_cast<float4*>(g_e)[(size_t)warp * (H / 4) + lane] = r;
}

// ---------------------------------------------------------------------------
// Pass 2: per-edge weighted dot product. One warp per edge.
// z[e] = scale * sum_h e[src][h] * d[h] * e[dst][h]
// NOTE: edge indices are int32 on the wire (JAX demotes int64 without x64).
// ---------------------------------------------------------------------------
__global__ void edge_dot(const int* __restrict__ esrc,
                         const int* __restrict__ edst,
                         const float* __restrict__ d,
                         const float* __restrict__ scale,
                         float* __restrict__ out,
                         int n_edges) {
    int warp = (blockIdx.x * blockDim.x + threadIdx.x) >> 5;
    int lane = threadIdx.x & 31;
    if (warp >= n_edges) return;

    int si = esrc[warp];
    int di = edst[warp];

    // d is tiny (512 B) -> L1-resident loads
    float4 dv = reinterpret_cast<const float4*>(d)[lane];

    float4 a = reinterpret_cast<const float4*>(g_e)[(size_t)si * (H / 4) + lane];
    float4 b = reinterpret_cast<const float4*>(g_e)[(size_t)di * (H / 4) + lane];

    float acc = a.x * dv.x * b.x;
    acc = fmaf(a.y * dv.y, b.y, acc);
    acc = fmaf(a.z * dv.z, b.z, acc);
    acc = fmaf(a.w * dv.w, b.w, acc);

#pragma unroll
    for (int o = 16; o > 0; o >>= 1) acc += __shfl_xor_sync(0xffffffffu, acc, o);

    if (lane == 0) out[warp] = acc * scale[0];
}

// ---------------------------------------------------------------------------
// Launch
// ---------------------------------------------------------------------------
extern "C" void kernel_launch(void* const* d_in, const int* in_sizes, int n_in,
                              void* d_out, int out_size) {
    const float* emb = (const float*)d_in[0];
    const int* esrc = (const int*)d_in[1];
    const int* edst = (const int*)d_in[2];
    const float* d = (const float*)d_in[3];
    const float* scale = (const float*)d_in[4];
    float* out = (float*)d_out;

    int n_nodes = in_sizes[0] / H;
    int n_edges = in_sizes[1];

    const int threads = 256;             // 8 warps/block
    int blocks1 = (n_nodes + 7) / 8;
    normalize_rows<<<blocks1, threads>>>(emb, n_nodes);

    int blocks2 = (n_edges + 7) / 8;
    edge_dot<<<blocks2, threads>>>(esrc, edst, d, scale, out, n_edges);
}

// round 3
// speedup vs baseline: 1.6665x; 1.6665x over previous
#include <cuda_runtime.h>
#include <cstdint>

// Problem constants (local_emb_D: N_NODES=100000, N_HIDDEN=128, N_EDGES=625000)
#define H 128
#define MAX_NODES 100000

// Scratch for normalized embeddings (51.2 MB) — device global, allocation-free.
__device__ float g_e[(size_t)MAX_NODES * H];

// ---------------------------------------------------------------------------
// Pass 1: L2-normalize each row. One warp per row; lane i handles float4 #i.
// ~102 MB HBM traffic -> ~13-17 us, already near the HBM floor.
// ---------------------------------------------------------------------------
__global__ void normalize_rows(const float* __restrict__ emb, int n_nodes) {
    int warp = (blockIdx.x * blockDim.x + threadIdx.x) >> 5;
    int lane = threadIdx.x & 31;
    if (warp >= n_nodes) return;

    const float4* row = reinterpret_cast<const float4*>(emb) + (size_t)warp * (H / 4);
    float4 v = row[lane];

    float s = v.x * v.x + v.y * v.y + v.z * v.z + v.w * v.w;
#pragma unroll
    for (int o = 16; o > 0; o >>= 1) s += __shfl_xor_sync(0xffffffffu, s, o);

    float inv = 1.0f / fmaxf(sqrtf(s), 1e-12f);

    float4 r = make_float4(v.x * inv, v.y * inv, v.z * inv, v.w * inv);
    reinterpret_cast<float4*>(g_e)[(size_t)warp * (H / 4) + lane] = r;
}

// ---------------------------------------------------------------------------
// Pass 2: per-edge weighted dot. 8 lanes per edge, 4 edges per warp.
// Each lane: 4 float4 gathers per table -> 8 LDG.128 in flight (MLP=8).
// Reduction: 3 shfl_xor per warp (covers 4 edges at once).
// z[e] = scale * sum_h e[src][h] * d[h] * e[dst][h]
// ---------------------------------------------------------------------------
__global__ void edge_dot(const int* __restrict__ esrc,
                         const int* __restrict__ edst,
                         const float* __restrict__ d,
                         const float* __restrict__ scale,
                         float* __restrict__ out,
                         int n_edges) {
    int warp = (blockIdx.x * blockDim.x + threadIdx.x) >> 5;
    int lane = threadIdx.x & 31;
    int grp  = lane >> 3;      // 0..3 : which edge within the warp
    int gl   = lane & 7;       // 0..7 : lane within the 8-lane group

    int edge = warp * 4 + grp;
    bool valid = (edge < n_edges);
    int eclamp = valid ? edge : (n_edges - 1);

    int si = esrc[eclamp];
    int di = edst[eclamp];

    const float4* A = reinterpret_cast<const float4*>(g_e) + (size_t)si * (H / 4);
    const float4* B = reinterpret_cast<const float4*>(g_e) + (size_t)di * (H / 4);
    const float4* D = reinterpret_cast<const float4*>(d);

    // Load all gathers up front for maximum MLP.
    float4 a0 = A[gl +  0], a1 = A[gl +  8], a2 = A[gl + 16], a3 = A[gl + 24];
    float4 b0 = B[gl +  0], b1 = B[gl +  8], b2 = B[gl + 16], b3 = B[gl + 24];
    float4 d0 = D[gl +  0], d1 = D[gl +  8], d2 = D[gl + 16], d3 = D[gl + 24];

    float acc;
    acc = a0.x * d0.x * b0.x;
    acc = fmaf(a0.y * d0.y, b0.y, acc);
    acc = fmaf(a0.z * d0.z, b0.z, acc);
    acc = fmaf(a0.w * d0.w, b0.w, acc);
    acc = fmaf(a1.x * d1.x, b1.x, acc);
    acc = fmaf(a1.y * d1.y, b1.y, acc);
    acc = fmaf(a1.z * d1.z, b1.z, acc);
    acc = fmaf(a1.w * d1.w, b1.w, acc);
    acc = fmaf(a2.x * d2.x, b2.x, acc);
    acc = fmaf(a2.y * d2.y, b2.y, acc);
    acc = fmaf(a2.z * d2.z, b2.z, acc);
    acc = fmaf(a2.w * d2.w, b2.w, acc);
    acc = fmaf(a3.x * d3.x, b3.x, acc);
    acc = fmaf(a3.y * d3.y, b3.y, acc);
    acc = fmaf(a3.z * d3.z, b3.z, acc);
    acc = fmaf(a3.w * d3.w, b3.w, acc);

    // Reduce across the 8-lane group (3 shfls serve all 4 edges in the warp).
    acc += __shfl_xor_sync(0xffffffffu, acc, 4);
    acc += __shfl_xor_sync(0xffffffffu, acc, 2);
    acc += __shfl_xor_sync(0xffffffffu, acc, 1);

    if (gl == 0 && valid) out[edge] = acc * scale[0];
}

// ---------------------------------------------------------------------------
// Launch
// ---------------------------------------------------------------------------
extern "C" void kernel_launch(void* const* d_in, const int* in_sizes, int n_in,
                              void* d_out, int out_size) {
    const float* emb = (const float*)d_in[0];
    const int* esrc = (const int*)d_in[1];
    const int* edst = (const int*)d_in[2];
    const float* d = (const float*)d_in[3];
    const float* scale = (const float*)d_in[4];
    float* out = (float*)d_out;

    int n_nodes = in_sizes[0] / H;
    int n_edges = in_sizes[1];

    const int threads = 256;                      // 8 warps/block
    int blocks1 = (n_nodes + 7) / 8;              // 1 row/warp
    normalize_rows<<<blocks1, threads>>>(emb, n_nodes);

    int warps_needed = (n_edges + 3) / 4;         // 4 edges/warp
    int blocks2 = (warps_needed + 7) / 8;
    edge_dot<<<blocks2, threads>>>(esrc, edst, d, scale, out, n_edges);
}

// round 4
// speedup vs baseline: 2.4077x; 1.4448x over previous
#include <cuda_runtime.h>
#include <cuda_fp16.h>
#include <cstdint>

// Problem constants (local_emb_D: N_NODES=100000, N_HIDDEN=128, N_EDGES=625000)
#define H 128
#define MAX_NODES 100000

// Normalized embeddings in fp16 (25.6 MB) — L2-resident gather table.
__device__ __half g_eh[(size_t)MAX_NODES * H];

// ---------------------------------------------------------------------------
// Pass 1: L2-normalize each row, store fp16. One warp per row.
// Lane i loads float4 #i (elements 4i..4i+3), writes 2x half2 (8 B).
// ---------------------------------------------------------------------------
__global__ void normalize_rows(const float* __restrict__ emb, int n_nodes) {
    int warp = (blockIdx.x * blockDim.x + threadIdx.x) >> 5;
    int lane = threadIdx.x & 31;
    if (warp >= n_nodes) return;

    const float4* row = reinterpret_cast<const float4*>(emb) + (size_t)warp * (H / 4);
    float4 v = row[lane];

    float s = v.x * v.x + v.y * v.y + v.z * v.z + v.w * v.w;
#pragma unroll
    for (int o = 16; o > 0; o >>= 1) s += __shfl_xor_sync(0xffffffffu, s, o);

    float inv = 1.0f / fmaxf(sqrtf(s), 1e-12f);

    __half2 h0 = __floats2half2_rn(v.x * inv, v.y * inv);
    __half2 h1 = __floats2half2_rn(v.z * inv, v.w * inv);

    uint2 packed;
    packed.x = *reinterpret_cast<unsigned int*>(&h0);
    packed.y = *reinterpret_cast<unsigned int*>(&h1);
    reinterpret_cast<uint2*>(g_eh)[(size_t)warp * (H / 4) + lane] = packed;
}

// ---------------------------------------------------------------------------
// Dot-product helper: one edge's partial sum for this lane.
// a0/a1, b0/b1: uint4 = 8 halves each (elements [gl*8,+8) and [64+gl*8,+8)).
// dv: 16 floats of d for the same elements. Accumulate fp32.
// ---------------------------------------------------------------------------
__device__ __forceinline__ float dot16(uint4 a0, uint4 a1, uint4 b0, uint4 b1,
                                       const float* dv) {
    float acc = 0.0f;
    const unsigned int* ua = &a0.x;
    const unsigned int* ub = &b0.x;
#pragma unroll
    for (int i = 0; i < 4; i++) {
        float2 fa = __half22float2(*reinterpret_cast<const __half2*>(&ua[i]));
        float2 fb = __half22float2(*reinterpret_cast<const __half2*>(&ub[i]));
        acc = fmaf(fa.x * dv[2 * i], fb.x, acc);
        acc = fmaf(fa.y * dv[2 * i + 1], fb.y, acc);
    }
    const unsigned int* ua1 = &a1.x;
    const unsigned int* ub1 = &b1.x;
#pragma unroll
    for (int i = 0; i < 4; i++) {
        float2 fa = __half22float2(*reinterpret_cast<const __half2*>(&ua1[i]));
        float2 fb = __half22float2(*reinterpret_cast<const __half2*>(&ub1[i]));
        acc = fmaf(fa.x * dv[8 + 2 * i], fb.x, acc);
        acc = fmaf(fa.y * dv[8 + 2 * i + 1], fb.y, acc);
    }
    return acc;
}

// ---------------------------------------------------------------------------
// Pass 2: 8 lanes per edge, 2 edges per lane-group -> 8 edges per warp.
// Each lane has 8 gather LDG.128 in flight (2 per table per edge).
// z[e] = scale * sum_h e[src][h] * d[h] * e[dst][h]
// ---------------------------------------------------------------------------
__global__ void edge_dot(const int* __restrict__ esrc,
                         const int* __restrict__ edst,
                         const float* __restrict__ d,
                         const float* __restrict__ scale,
                         float* __restrict__ out,
                         int n_edges) {
    int warp = (blockIdx.x * blockDim.x + threadIdx.x) >> 5;
    int lane = threadIdx.x & 31;
    int grp  = lane >> 3;      // 0..3
    int gl   = lane & 7;       // 0..7

    int e0 = warp * 8 + grp;       // first edge for this group
    int e1 = e0 + 4;               // second edge
    bool v0 = (e0 < n_edges);
    bool v1 = (e1 < n_edges);
    int c0 = v0 ? e0 : 0;
    int c1 = v1 ? e1 : 0;

    int si0 = esrc[c0], di0 = edst[c0];
    int si1 = esrc[c1], di1 = edst[c1];

    // Row pointers (fp16 rows: 256 B = 16 uint4; lane gl covers uint4 gl and gl+8)
    const uint4* A0 = reinterpret_cast<const uint4*>(g_eh) + (size_t)si0 * (H / 8);
    const uint4* B0 = reinterpret_cast<const uint4*>(g_eh) + (size_t)di0 * (H / 8);
    const uint4* A1 = reinterpret_cast<const uint4*>(g_eh) + (size_t)si1 * (H / 8);
    const uint4* B1 = reinterpret_cast<const uint4*>(g_eh) + (size_t)di1 * (H / 8);

    // Issue all 8 gathers up front (MLP=8).
    uint4 a00 = A0[gl], a01 = A0[gl + 8];
    uint4 b00 = B0[gl], b01 = B0[gl + 8];
    uint4 a10 = A1[gl], a11 = A1[gl + 8];
    uint4 b10 = B1[gl], b11 = B1[gl + 8];

    // d for this lane's 16 elements: [gl*8, +8) and [64+gl*8, +8). L1-resident.
    float dv[16];
    {
        const float4* D = reinterpret_cast<const float4*>(d);
        float4 d0 = D[gl * 2], d1 = D[gl * 2 + 1];
        float4 d2 = D[16 + gl * 2], d3 = D[16 + gl * 2 + 1];
        dv[0] = d0.x; dv[1] = d0.y; dv[2] = d0.z; dv[3] = d0.w;
        dv[4] = d1.x; dv[5] = d1.y; dv[6] = d1.z; dv[7] = d1.w;
        dv[8] = d2.x; dv[9] = d2.y; dv[10] = d2.z; dv[11] = d2.w;
        dv[12] = d3.x; dv[13] = d3.y; dv[14] = d3.z; dv[15] = d3.w;
    }

    float acc0 = dot16(a00, a01, b00, b01, dv);
    float acc1 = dot16(a10, a11, b10, b11, dv);

    // Reduce each acc across the 8-lane group (shfls serve all 4 groups).
    acc0 += __shfl_xor_sync(0xffffffffu, acc0, 4);
    acc0 += __shfl_xor_sync(0xffffffffu, acc0, 2);
    acc0 += __shfl_xor_sync(0xffffffffu, acc0, 1);
    acc1 += __shfl_xor_sync(0xffffffffu, acc1, 4);
    acc1 += __shfl_xor_sync(0xffffffffu, acc1, 2);
    acc1 += __shfl_xor_sync(0xffffffffu, acc1, 1);

    float sc = scale[0];
    if (gl == 0) {
        if (v0) out[e0] = acc0 * sc;
        if (v1) out[e1] = acc1 * sc;
    }
}

// ---------------------------------------------------------------------------
// Launch
// ---------------------------------------------------------------------------
extern "C" void kernel_launch(void* const* d_in, const int* in_sizes, int n_in,
                              void* d_out, int out_size) {
    const float* emb = (const float*)d_in[0];
    const int* esrc = (const int*)d_in[1];
    const int* edst = (const int*)d_in[2];
    const float* d = (const float*)d_in[3];
    const float* scale = (const float*)d_in[4];
    float* out = (float*)d_out;

    int n_nodes = in_sizes[0] / H;
    int n_edges = in_sizes[1];

    const int threads = 256;                      // 8 warps/block
    int blocks1 = (n_nodes + 7) / 8;              // 1 row/warp
    normalize_rows<<<blocks1, threads>>>(emb, n_nodes);

    int warps_needed = (n_edges + 7) / 8;         // 8 edges/warp
    int blocks2 = (warps_needed + 7) / 8;
    edge_dot<<<blocks2, threads>>>(esrc, edst, d, scale, out, n_edges);
}